// round 4
// baseline (speedup 1.0000x reference)
#include <cuda_runtime.h>
#include <cstdint>

#define BATCH  4096
#define NIN    784
#define H1     100
#define H1P    128
#define H2     10
#define NSTEP  100
#define TBEGIN 20
#define KT     56            // k-chunk per smem stage
#define NCHUNK 14            // 784 / 56
#define NK4    14            // KT / 4
#define RT     16            // batch rows per layer-1 CTA
#define L1CTAS 256           // 4096 / 16
#define L2CTAS 32            // 4096 / 128
#define XI_ELE (RT * KT)     // 896 gated inputs per chunk
#define WS_ELE (KT * H1P)    // 7168 weight floats per chunk
#define DYN_SMEM ((2 * WS_ELE + 2 * XI_ELE) * 4)   // 64512 bytes

// ---------------- device globals ----------------
__device__ float g_Wg[NIN * H1P];            // interleaved: [k>>2][h][k&3]
__device__ float g_inner1[BATCH * H1P];
__device__ float g_outer1[2][BATCH * H1P];
__device__ float g_inner2[BATCH * H2];
__device__ float g_acc[BATCH * H2];

// ---------------- packed fp32x2 FMA ----------------
__device__ __forceinline__ void ffma2(unsigned long long &a,
                                      unsigned long long xv,
                                      unsigned long long wv) {
    asm("fma.rn.f32x2 %0, %1, %2, %0;" : "+l"(a) : "l"(xv), "l"(wv));
}
__device__ __forceinline__ float fold2(unsigned long long a) {
    float lo, hi;
    asm("mov.b64 {%0,%1}, %2;" : "=f"(lo), "=f"(hi) : "l"(a));
    return lo + hi;
}

// ---------------- threefry2x32 (JAX-exact) ----------------
__device__ __forceinline__ void tf2x32(unsigned k0, unsigned k1,
                                       unsigned x0, unsigned x1,
                                       unsigned &o0, unsigned &o1) {
    unsigned ks2 = k0 ^ k1 ^ 0x1BD11BDAu;
    x0 += k0; x1 += k1;
#define TFR(r) { x0 += x1; x1 = __funnelshift_l(x1, x1, (r)); x1 ^= x0; }
    TFR(13) TFR(15) TFR(26) TFR(6);  x0 += k1;  x1 += ks2 + 1u;
    TFR(17) TFR(29) TFR(16) TFR(24); x0 += ks2; x1 += k0 + 2u;
    TFR(13) TFR(15) TFR(26) TFR(6);  x0 += k0;  x1 += k1 + 3u;
    TFR(17) TFR(29) TFR(16) TFR(24); x0 += k1;  x1 += ks2 + 4u;
    TFR(13) TFR(15) TFR(26) TFR(6);  x0 += ks2; x1 += k0 + 5u;
#undef TFR
    o0 = x0; o1 = x1;
}
__device__ __forceinline__ float tf_uniform(unsigned k0, unsigned k1, unsigned idx) {
    unsigned o0, o1;
    tf2x32(k0, k1, 0u, idx, o0, o1);
    unsigned bits = o0 ^ o1;
    return __uint_as_float((bits >> 9) | 0x3f800000u) - 1.0f;
}

// ---------------- init ----------------
__global__ void init_k(const float* __restrict__ W1) {
    int stride = gridDim.x * blockDim.x;
    int tid = blockIdx.x * blockDim.x + threadIdx.x;
    for (int i = tid; i < BATCH * H1P; i += stride) {
        g_inner1[i] = 0.0f; g_outer1[0][i] = 0.0f; g_outer1[1][i] = 0.0f;
    }
    for (int i = tid; i < BATCH * H2; i += stride) {
        g_inner2[i] = 0.0f; g_acc[i] = 0.0f;
    }
    for (int i = tid; i < NIN * H1P; i += stride) {
        int k = i / H1P;
        int h = i - k * H1P;
        g_Wg[(k >> 2) * (H1P * 4) + h * 4 + (k & 3)] = (h < H1) ? W1[k * H1 + h] : 0.0f;
    }
}

// ---------------- per-step kernel ----------------
__global__ void __launch_bounds__(128, 2)
step_k(const float* __restrict__ x,
       const float* __restrict__ b1,
       const float* __restrict__ W2,
       const float* __restrict__ b2,
       unsigned key0, unsigned key1, int t)
{
    extern __shared__ float dyn[];
    float* sh_ws = dyn;                      // [2][WS_ELE]
    float* sh_xi = dyn + 2 * WS_ELE;         // [2][XI_ELE]

    const int tid = threadIdx.x;

    if (blockIdx.x < L1CTAS) {
        // ================= LAYER 1 =================
        const int lane = tid & 31;
        const int rq   = tid >> 5;           // warp = row group (4 rows)
        const int r0   = blockIdx.x * RT;
        float* __restrict__ outw = g_outer1[t & 1];

        // 16 packed accumulators: [4 rows][4 h] (h = lane + 32*j)
        unsigned long long acc2[4][4];
        #pragma unroll
        for (int a = 0; a < 4; ++a)
            #pragma unroll
            for (int b = 0; b < 4; ++b) acc2[a][b] = 0ull;

        float4 wreg[14];
        float  xreg[7];

        // prologue: load chunk 0 into regs
        {
            const float4* wsrc = (const float4*)g_Wg;
            #pragma unroll
            for (int i = 0; i < 14; ++i) wreg[i] = wsrc[tid + i * 128];
            #pragma unroll
            for (int i = 0; i < 7; ++i) {
                int f = tid + i * 128;
                xreg[i] = x[(r0 + f / KT) * NIN + (f % KT)];
            }
        }

        for (int c = 0; c < NCHUNK; ++c) {
            const int buf = c & 1;
            // ---- stage chunk c from regs into smem buffer 'buf' ----
            {
                float4* wdst = (float4*)(sh_ws + buf * WS_ELE);
                #pragma unroll
                for (int i = 0; i < 14; ++i) wdst[tid + i * 128] = wreg[i];
                const int kc = c * KT;
                float* xdst = sh_xi + buf * XI_ELE;
                #pragma unroll
                for (int i = 0; i < 7; ++i) {
                    int f = tid + i * 128;
                    unsigned j = (unsigned)((r0 + f / KT) * NIN + kc + (f % KT));
                    xdst[f] = tf_uniform(key0, key1, j) * xreg[i];
                }
            }
            // ---- prefetch chunk c+1 into regs (hidden under GEMM) ----
            if (c + 1 < NCHUNK) {
                const float4* wsrc = (const float4*)(g_Wg + (c + 1) * WS_ELE);
                #pragma unroll
                for (int i = 0; i < 14; ++i) wreg[i] = wsrc[tid + i * 128];
                const int kn = (c + 1) * KT;
                #pragma unroll
                for (int i = 0; i < 7; ++i) {
                    int f = tid + i * 128;
                    xreg[i] = x[(r0 + f / KT) * NIN + kn + (f % KT)];
                }
            }
            __syncthreads();   // staging of buf complete; prior buf reads done

            // ---- GEMM over chunk c: 4 rows x 128 h per warp ----
            const float* ws = sh_ws + buf * WS_ELE;
            const float* xs = sh_xi + buf * XI_ELE;
            #pragma unroll
            for (int k4 = 0; k4 < NK4; ++k4) {
                ulonglong2 xv[4];
                #pragma unroll
                for (int rr = 0; rr < 4; ++rr)
                    xv[rr] = *(const ulonglong2*)&xs[(rq * 4 + rr) * KT + k4 * 4];
                #pragma unroll
                for (int j = 0; j < 4; ++j) {
                    ulonglong2 wv = *(const ulonglong2*)&ws[k4 * (H1P * 4) + (lane + 32 * j) * 4];
                    #pragma unroll
                    for (int rr = 0; rr < 4; ++rr) {
                        ffma2(acc2[rr][j], xv[rr].x, wv.x);
                        ffma2(acc2[rr][j], xv[rr].y, wv.y);
                    }
                }
            }
        }

        // ---- LIF update for layer 1 ----
        #pragma unroll
        for (int rr = 0; rr < 4; ++rr) {
            int r = r0 + rq * 4 + rr;
            #pragma unroll
            for (int j = 0; j < 4; ++j) {
                int h = lane + 32 * j;
                float exc = fold2(acc2[rr][j]) + ((h < H1) ? b1[h] : 0.0f);
                float pi  = g_inner1[r * H1P + h];
                float ni  = fmaf(pi, 0.9f, exc);
                float d   = ni - 1.0f;
                float ou  = d > 0.0f ? d : 0.0f;
                outw[r * H1P + h] = ou;
                if (ou > 0.0f) ni = ni - 1.5f * ni;   // penalty reset
                g_inner1[r * H1P + h] = ni;
            }
        }
    } else {
        // ================= LAYER 2 =================
        float* sh_w2 = dyn;                  // 1000 floats
        float* sh_b2 = dyn + H1 * H2;
        for (int i = tid; i < H1 * H2; i += 128) sh_w2[i] = W2[i];
        if (tid < H2) sh_b2[tid] = b2[tid];
        __syncthreads();

        int r = (blockIdx.x - L1CTAS) * 128 + tid;
        const float* __restrict__ po = g_outer1[(t & 1) ^ 1] + r * H1P;  // delayed

        float s[H2];
        #pragma unroll
        for (int h2 = 0; h2 < H2; ++h2) s[h2] = sh_b2[h2];

        for (int k = 0; k < H1; k += 4) {
            float4 p = *(const float4*)&po[k];
            #pragma unroll
            for (int h2 = 0; h2 < H2; ++h2) {
                float a = s[h2];
                a = fmaf(p.x, sh_w2[(k + 0) * H2 + h2], a);
                a = fmaf(p.y, sh_w2[(k + 1) * H2 + h2], a);
                a = fmaf(p.z, sh_w2[(k + 2) * H2 + h2], a);
                a = fmaf(p.w, sh_w2[(k + 3) * H2 + h2], a);
                s[h2] = a;
            }
        }

        #pragma unroll
        for (int h2 = 0; h2 < H2; ++h2) {
            float pi = g_inner2[r * H2 + h2];
            if (t >= TBEGIN) g_acc[r * H2 + h2] += pi;   // delayed state
            float ni = fmaf(pi, 0.9f, s[h2]);
            float d  = ni - 1.0f;
            if (d > 0.0f) ni = ni - 1.5f * ni;
            g_inner2[r * H2 + h2] = ni;
        }
    }
}

// ---------------- finalize: log_softmax ----------------
__global__ void final_k(float* __restrict__ out) {
    int r = blockIdx.x * blockDim.x + threadIdx.x;
    if (r >= BATCH) return;
    float v[H2];
    float m = -3.402823466e38f;
    #pragma unroll
    for (int c = 0; c < H2; ++c) { v[c] = g_acc[r * H2 + c]; m = fmaxf(m, v[c]); }
    float sum = 0.0f;
    #pragma unroll
    for (int c = 0; c < H2; ++c) sum += expf(v[c] - m);
    float l = logf(sum);
    #pragma unroll
    for (int c = 0; c < H2; ++c) out[r * H2 + c] = v[c] - m - l;
}

// ---------------- host threefry ----------------
static inline unsigned h_rotl(unsigned v, int r) { return (v << r) | (v >> (32 - r)); }
static void host_tf2x32(unsigned k0, unsigned k1, unsigned x0, unsigned x1,
                        unsigned* o0, unsigned* o1) {
    unsigned ks2 = k0 ^ k1 ^ 0x1BD11BDAu;
    x0 += k0; x1 += k1;
#define HTFR(r) { x0 += x1; x1 = h_rotl(x1, (r)); x1 ^= x0; }
    HTFR(13) HTFR(15) HTFR(26) HTFR(6);  x0 += k1;  x1 += ks2 + 1u;
    HTFR(17) HTFR(29) HTFR(16) HTFR(24); x0 += ks2; x1 += k0 + 2u;
    HTFR(13) HTFR(15) HTFR(26) HTFR(6);  x0 += k0;  x1 += k1 + 3u;
    HTFR(17) HTFR(29) HTFR(16) HTFR(24); x0 += k1;  x1 += ks2 + 4u;
    HTFR(13) HTFR(15) HTFR(26) HTFR(6);  x0 += ks2; x1 += k0 + 5u;
#undef HTFR
    *o0 = x0; *o1 = x1;
}

extern "C" void kernel_launch(void* const* d_in, const int* in_sizes, int n_in,
                              void* d_out, int out_size) {
    const float* x  = (const float*)d_in[0];
    const float* W1 = (const float*)d_in[1];
    const float* b1 = (const float*)d_in[2];
    const float* W2 = (const float*)d_in[3];
    const float* b2 = (const float*)d_in[4];
    float* out = (float*)d_out;

    cudaFuncSetAttribute(step_k, cudaFuncAttributeMaxDynamicSharedMemorySize, DYN_SMEM);

    init_k<<<1024, 256>>>(W1);

    for (int t = 0; t < NSTEP; ++t) {
        unsigned k0, k1;
        host_tf2x32(0u, 42u, 0u, (unsigned)t, &k0, &k1);
        step_k<<<L1CTAS + L2CTAS, 128, DYN_SMEM>>>(x, b1, W2, b2, k0, k1, t);
    }

    final_k<<<16, 256>>>(out);
    (void)in_sizes; (void)n_in; (void)out_size;
}

// round 5
// speedup vs baseline: 1.0458x; 1.0458x over previous
#include <cuda_runtime.h>
#include <cstdint>

#define BATCH  4096
#define NIN    784
#define H1     100
#define H1P    128
#define H2     10
#define NSTEP  100
#define TBEGIN 20
#define KT     56                 // k-chunk per smem stage
#define NCHUNK 14                 // 784 / 56
#define RT     32                 // batch rows per layer-1 CTA
#define L1CTAS 128                // 4096 / 32
#define L2CTAS 16                 // 4096 / 256
#define WS_ELE (KT * H1P)         // 7168 W floats per chunk
#define XI_ELE (KT * RT)          // 1792 dup'd 8B entries per chunk
#define DYN_SMEM (2 * WS_ELE * 4 + 2 * XI_ELE * 8)   // 57344 + 28672 = 86016 B

// ---------------- device globals ----------------
__device__ float g_W1p[NIN * H1P];           // padded W1 [k][128 h]
__device__ float g_xT[NIN * BATCH];          // transposed input [k][row]
__device__ float g_inner1[BATCH * H1P];
__device__ float g_outer1[2][BATCH * H1P];
__device__ float g_inner2[BATCH * H2];
__device__ float g_acc[BATCH * H2];

// ---------------- packed fp32x2 FMA ----------------
__device__ __forceinline__ void ffma2(unsigned long long &a,
                                      unsigned long long xv,
                                      unsigned long long wv) {
    asm("fma.rn.f32x2 %0, %1, %2, %0;" : "+l"(a) : "l"(xv), "l"(wv));
}
__device__ __forceinline__ void unpack2(unsigned long long a, float &lo, float &hi) {
    asm("mov.b64 {%0,%1}, %2;" : "=f"(lo), "=f"(hi) : "l"(a));
}
__device__ __forceinline__ unsigned long long dup2(float v) {
    unsigned long long d;
    asm("mov.b64 %0, {%1,%1};" : "=l"(d) : "f"(v));
    return d;
}

// ---------------- threefry2x32 (JAX-exact) ----------------
__device__ __forceinline__ void tf2x32(unsigned k0, unsigned k1,
                                       unsigned x0, unsigned x1,
                                       unsigned &o0, unsigned &o1) {
    unsigned ks2 = k0 ^ k1 ^ 0x1BD11BDAu;
    x0 += k0; x1 += k1;
#define TFR(r) { x0 += x1; x1 = __funnelshift_l(x1, x1, (r)); x1 ^= x0; }
    TFR(13) TFR(15) TFR(26) TFR(6);  x0 += k1;  x1 += ks2 + 1u;
    TFR(17) TFR(29) TFR(16) TFR(24); x0 += ks2; x1 += k0 + 2u;
    TFR(13) TFR(15) TFR(26) TFR(6);  x0 += k0;  x1 += k1 + 3u;
    TFR(17) TFR(29) TFR(16) TFR(24); x0 += k1;  x1 += ks2 + 4u;
    TFR(13) TFR(15) TFR(26) TFR(6);  x0 += ks2; x1 += k0 + 5u;
#undef TFR
    o0 = x0; o1 = x1;
}
__device__ __forceinline__ float tf_uniform(unsigned k0, unsigned k1, unsigned idx) {
    unsigned o0, o1;
    tf2x32(k0, k1, 0u, idx, o0, o1);
    unsigned bits = o0 ^ o1;
    return __uint_as_float((bits >> 9) | 0x3f800000u) - 1.0f;
}

// ---------------- init: states, padded W1, transposed x ----------------
__global__ void init_k(const float* __restrict__ W1, const float* __restrict__ x) {
    int stride = gridDim.x * blockDim.x;
    int tid = blockIdx.x * blockDim.x + threadIdx.x;
    for (int i = tid; i < BATCH * H1P; i += stride) {
        g_inner1[i] = 0.0f; g_outer1[0][i] = 0.0f; g_outer1[1][i] = 0.0f;
    }
    for (int i = tid; i < BATCH * H2; i += stride) {
        g_inner2[i] = 0.0f; g_acc[i] = 0.0f;
    }
    for (int i = tid; i < NIN * H1P; i += stride) {
        int k = i >> 7, h = i & 127;
        g_W1p[i] = (h < H1) ? W1[k * H1 + h] : 0.0f;
    }
    for (int i = tid; i < NIN * BATCH; i += stride) {
        int k = i >> 12, r = i & 4095;          // i = k*4096 + r
        g_xT[i] = x[r * NIN + k];
    }
}

// ---------------- per-step kernel: warp-specialized ----------------
__global__ void __launch_bounds__(256, 1)
step_k(const float* __restrict__ b1,
       const float* __restrict__ W2,
       const float* __restrict__ b2,
       unsigned key0, unsigned key1, int t)
{
    extern __shared__ float dyn[];
    float* sh_ws = dyn;                                        // [2][WS_ELE]
    unsigned long long* sh_xi =
        (unsigned long long*)(dyn + 2 * WS_ELE);               // [2][XI_ELE]

    const int tid = threadIdx.x;

    if (blockIdx.x < L1CTAS) {
        const int r0 = blockIdx.x * RT;

        if (tid < 128) {
            // ============ CONSUMER: GEMM 32 rows x 128 h ============
            const int lane  = tid & 31;
            const int wrow0 = (tid >> 5) * 8;          // warp 0..3 -> rows 0,8,16,24
            float* __restrict__ outw = g_outer1[t & 1];

            // acc2[row 0..7][hpair 0..1]: (h=4*lane + 2*hp, +1)
            unsigned long long acc2[8][2];
            #pragma unroll
            for (int a = 0; a < 8; ++a) { acc2[a][0] = 0ull; acc2[a][1] = 0ull; }

            for (int c = 0; c < NCHUNK; ++c) {
                __syncthreads();                        // buf[c&1] is ready
                const float* ws = sh_ws + (c & 1) * WS_ELE;
                const unsigned long long* xs = sh_xi + (c & 1) * XI_ELE;

                #pragma unroll 4
                for (int k = 0; k < KT; ++k) {
                    const ulonglong2* ap = (const ulonglong2*)(xs + k * RT + wrow0);
                    ulonglong2 aA = ap[0];   // rows 0,1 (dup'd)
                    ulonglong2 aB = ap[1];   // rows 2,3
                    ulonglong2 aC = ap[2];   // rows 4,5
                    ulonglong2 aD = ap[3];   // rows 6,7
                    ulonglong2 bv = *(const ulonglong2*)&ws[k * H1P + lane * 4];
                    ffma2(acc2[0][0], aA.x, bv.x); ffma2(acc2[0][1], aA.x, bv.y);
                    ffma2(acc2[1][0], aA.y, bv.x); ffma2(acc2[1][1], aA.y, bv.y);
                    ffma2(acc2[2][0], aB.x, bv.x); ffma2(acc2[2][1], aB.x, bv.y);
                    ffma2(acc2[3][0], aB.y, bv.x); ffma2(acc2[3][1], aB.y, bv.y);
                    ffma2(acc2[4][0], aC.x, bv.x); ffma2(acc2[4][1], aC.x, bv.y);
                    ffma2(acc2[5][0], aC.y, bv.x); ffma2(acc2[5][1], aC.y, bv.y);
                    ffma2(acc2[6][0], aD.x, bv.x); ffma2(acc2[6][1], aD.x, bv.y);
                    ffma2(acc2[7][0], aD.y, bv.x); ffma2(acc2[7][1], aD.y, bv.y);
                }
            }

            // ---- LIF epilogue: 8 rows x 4 h per lane ----
            float4 bias = make_float4(0.f, 0.f, 0.f, 0.f);
            if (lane < 25) bias = *(const float4*)&b1[lane * 4];
            #pragma unroll
            for (int rr = 0; rr < 8; ++rr) {
                int r = r0 + wrow0 + rr;
                float e0, e1, e2, e3;
                unpack2(acc2[rr][0], e0, e1);
                unpack2(acc2[rr][1], e2, e3);
                e0 += bias.x; e1 += bias.y; e2 += bias.z; e3 += bias.w;
                float4 piv = *(const float4*)&g_inner1[r * H1P + lane * 4];
                float n0 = fmaf(piv.x, 0.9f, e0);
                float n1 = fmaf(piv.y, 0.9f, e1);
                float n2 = fmaf(piv.z, 0.9f, e2);
                float n3 = fmaf(piv.w, 0.9f, e3);
                float o0 = fmaxf(n0 - 1.0f, 0.0f);
                float o1 = fmaxf(n1 - 1.0f, 0.0f);
                float o2 = fmaxf(n2 - 1.0f, 0.0f);
                float o3 = fmaxf(n3 - 1.0f, 0.0f);
                *(float4*)&outw[r * H1P + lane * 4] = make_float4(o0, o1, o2, o3);
                if (o0 > 0.0f) n0 = -0.5f * n0;
                if (o1 > 0.0f) n1 = -0.5f * n1;
                if (o2 > 0.0f) n2 = -0.5f * n2;
                if (o3 > 0.0f) n3 = -0.5f * n3;
                *(float4*)&g_inner1[r * H1P + lane * 4] = make_float4(n0, n1, n2, n3);
            }
        } else {
            // ============ PRODUCER: RNG + staging ============
            const int ptid = tid - 128;                 // 0..127

            // prologue: fill chunk 0 into buf 0
            {
                const float4* wsrc = (const float4*)g_W1p;
                float4* wdst = (float4*)sh_ws;
                #pragma unroll
                for (int i = 0; i < 14; ++i) wdst[ptid + i * 128] = wsrc[ptid + i * 128];
                #pragma unroll 2
                for (int i = 0; i < 14; ++i) {
                    int idx = i * 128 + ptid;
                    int k = idx >> 5, row = idx & 31;
                    float xv = g_xT[k * BATCH + r0 + row];
                    unsigned j = (unsigned)((r0 + row) * NIN + k);
                    sh_xi[idx] = dup2(tf_uniform(key0, key1, j) * xv);
                }
            }

            for (int c = 0; c < NCHUNK; ++c) {
                __syncthreads();                        // consumers now own buf[c&1]
                if (c + 1 < NCHUNK) {
                    const int buf = (c + 1) & 1;
                    const int kc  = (c + 1) * KT;
                    const float4* wsrc = (const float4*)(g_W1p + (c + 1) * WS_ELE);
                    float4* wdst = (float4*)(sh_ws + buf * WS_ELE);
                    #pragma unroll
                    for (int i = 0; i < 14; ++i) wdst[ptid + i * 128] = wsrc[ptid + i * 128];
                    unsigned long long* xdst = sh_xi + buf * XI_ELE;
                    #pragma unroll 2
                    for (int i = 0; i < 14; ++i) {
                        int idx = i * 128 + ptid;
                        int k = idx >> 5, row = idx & 31;
                        float xv = g_xT[(kc + k) * BATCH + r0 + row];
                        unsigned j = (unsigned)((r0 + row) * NIN + kc + k);
                        xdst[idx] = dup2(tf_uniform(key0, key1, j) * xv);
                    }
                }
            }
        }
    } else {
        // ================= LAYER 2 =================
        float* sh_w2 = dyn;
        float* sh_b2 = dyn + H1 * H2;
        for (int i = tid; i < H1 * H2; i += 256) sh_w2[i] = W2[i];
        if (tid < H2) sh_b2[tid] = b2[tid];
        __syncthreads();

        int r = (blockIdx.x - L1CTAS) * 256 + tid;
        const float* __restrict__ po = g_outer1[(t & 1) ^ 1] + r * H1P;  // delayed

        float s[H2];
        #pragma unroll
        for (int h2 = 0; h2 < H2; ++h2) s[h2] = sh_b2[h2];

        for (int k = 0; k < H1; k += 4) {
            float4 p = *(const float4*)&po[k];
            #pragma unroll
            for (int h2 = 0; h2 < H2; ++h2) {
                float a = s[h2];
                a = fmaf(p.x, sh_w2[(k + 0) * H2 + h2], a);
                a = fmaf(p.y, sh_w2[(k + 1) * H2 + h2], a);
                a = fmaf(p.z, sh_w2[(k + 2) * H2 + h2], a);
                a = fmaf(p.w, sh_w2[(k + 3) * H2 + h2], a);
                s[h2] = a;
            }
        }

        #pragma unroll
        for (int h2 = 0; h2 < H2; ++h2) {
            float pi = g_inner2[r * H2 + h2];
            if (t >= TBEGIN) g_acc[r * H2 + h2] += pi;   // delayed state
            float ni = fmaf(pi, 0.9f, s[h2]);
            float d  = ni - 1.0f;
            if (d > 0.0f) ni = ni - 1.5f * ni;
            g_inner2[r * H2 + h2] = ni;
        }
    }
}

// ---------------- finalize: log_softmax ----------------
__global__ void final_k(float* __restrict__ out) {
    int r = blockIdx.x * blockDim.x + threadIdx.x;
    if (r >= BATCH) return;
    float v[H2];
    float m = -3.402823466e38f;
    #pragma unroll
    for (int c = 0; c < H2; ++c) { v[c] = g_acc[r * H2 + c]; m = fmaxf(m, v[c]); }
    float sum = 0.0f;
    #pragma unroll
    for (int c = 0; c < H2; ++c) sum += expf(v[c] - m);
    float l = logf(sum);
    #pragma unroll
    for (int c = 0; c < H2; ++c) out[r * H2 + c] = v[c] - m - l;
}

// ---------------- host threefry ----------------
static inline unsigned h_rotl(unsigned v, int r) { return (v << r) | (v >> (32 - r)); }
static void host_tf2x32(unsigned k0, unsigned k1, unsigned x0, unsigned x1,
                        unsigned* o0, unsigned* o1) {
    unsigned ks2 = k0 ^ k1 ^ 0x1BD11BDAu;
    x0 += k0; x1 += k1;
#define HTFR(r) { x0 += x1; x1 = h_rotl(x1, (r)); x1 ^= x0; }
    HTFR(13) HTFR(15) HTFR(26) HTFR(6);  x0 += k1;  x1 += ks2 + 1u;
    HTFR(17) HTFR(29) HTFR(16) HTFR(24); x0 += ks2; x1 += k0 + 2u;
    HTFR(13) HTFR(15) HTFR(26) HTFR(6);  x0 += k0;  x1 += k1 + 3u;
    HTFR(17) HTFR(29) HTFR(16) HTFR(24); x0 += k1;  x1 += ks2 + 4u;
    HTFR(13) HTFR(15) HTFR(26) HTFR(6);  x0 += ks2; x1 += k0 + 5u;
#undef HTFR
    *o0 = x0; *o1 = x1;
}

extern "C" void kernel_launch(void* const* d_in, const int* in_sizes, int n_in,
                              void* d_out, int out_size) {
    const float* x  = (const float*)d_in[0];
    const float* W1 = (const float*)d_in[1];
    const float* b1 = (const float*)d_in[2];
    const float* W2 = (const float*)d_in[3];
    const float* b2 = (const float*)d_in[4];
    float* out = (float*)d_out;

    cudaFuncSetAttribute(step_k, cudaFuncAttributeMaxDynamicSharedMemorySize, DYN_SMEM);

    init_k<<<1024, 256>>>(W1, x);

    for (int t = 0; t < NSTEP; ++t) {
        unsigned k0, k1;
        host_tf2x32(0u, 42u, 0u, (unsigned)t, &k0, &k1);
        step_k<<<L1CTAS + L2CTAS, 256, DYN_SMEM>>>(b1, W2, b2, k0, k1, t);
    }

    final_k<<<16, 256>>>(out);
    (void)in_sizes; (void)n_in; (void)out_size;
}